// round 8
// baseline (speedup 1.0000x reference)
#include <cuda_runtime.h>
#include <cstdint>

#define N_NODES 40000
#define N_EDGES 640000
#define D_FEAT  128

// ---------------------------------------------------------------------------
// Static scratch (no cudaMalloc allowed): counting-sort CSR build.
// ---------------------------------------------------------------------------
__device__ int   g_count  [N_NODES];
__device__ int   g_offsets[N_NODES + 1];
__device__ int   g_cursor [N_NODES];
__device__ int   g_scol   [N_EDGES];
__device__ float g_sval   [N_EDGES];

// ---------------------------------------------------------------------------
// K1: zero the per-row counters.
// ---------------------------------------------------------------------------
__global__ void zero_counts_kernel()
{
    int i = blockIdx.x * blockDim.x + threadIdx.x;
    if (i < N_NODES) g_count[i] = 0;
}

// ---------------------------------------------------------------------------
// K2: histogram of edge destination rows.
// ---------------------------------------------------------------------------
__global__ void __launch_bounds__(256) hist_kernel(const int* __restrict__ edge_rows)
{
    int i = blockIdx.x * blockDim.x + threadIdx.x;
    if (i < N_EDGES) atomicAdd(&g_count[edge_rows[i]], 1);
}

// ---------------------------------------------------------------------------
// K3: single-block exclusive scan of 40000 counts -> offsets (+ cursor copy).
// 1024 threads, 40 contiguous counts per thread; two-level warp scan.
// ---------------------------------------------------------------------------
__global__ void __launch_bounds__(1024) scan_kernel()
{
    __shared__ int warp_sums[32];

    const int t     = threadIdx.x;
    const int lane  = t & 31;
    const int wid   = t >> 5;
    const int CHUNK = 40;                       // 1024 * 40 >= 40000
    const int begin = t * CHUNK;
    const int end   = min(begin + CHUNK, N_NODES);

    int s = 0;
    for (int i = begin; i < end; i++) s += g_count[i];

    // inclusive scan of per-thread sums across the block
    int v = s;
    #pragma unroll
    for (int o = 1; o < 32; o <<= 1) {
        int n = __shfl_up_sync(0xffffffffu, v, o);
        if (lane >= o) v += n;
    }
    if (lane == 31) warp_sums[wid] = v;
    __syncthreads();
    if (wid == 0) {
        int w = warp_sums[lane];
        #pragma unroll
        for (int o = 1; o < 32; o <<= 1) {
            int n = __shfl_up_sync(0xffffffffu, w, o);
            if (lane >= o) w += n;
        }
        warp_sums[lane] = w;
    }
    __syncthreads();

    int excl = v - s + (wid > 0 ? warp_sums[wid - 1] : 0);

    int run = excl;
    for (int i = begin; i < end; i++) {
        g_offsets[i] = run;
        g_cursor[i]  = run;
        run += g_count[i];
    }
    if (end == N_NODES && begin < N_NODES) g_offsets[N_NODES] = run;  // == N_EDGES
}

// ---------------------------------------------------------------------------
// K4: permute edges into row-sorted order (counting-sort scatter).
// ---------------------------------------------------------------------------
__global__ void __launch_bounds__(256) permute_kernel(
    const int*   __restrict__ edge_rows,
    const int*   __restrict__ edge_cols,
    const float* __restrict__ adj_vals)
{
    int i = blockIdx.x * blockDim.x + threadIdx.x;
    if (i >= N_EDGES) return;
    const int   r = edge_rows[i];
    const int   c = edge_cols[i];
    const float v = adj_vals[i];
    const int pos = atomicAdd(&g_cursor[r], 1);
    g_scol[pos] = c;
    g_sval[pos] = v;
}

// ---------------------------------------------------------------------------
// K5: warp-per-node gather. Each lane owns one float4 of the 128-feature row.
// Edges are loaded cooperatively (one per lane) and shuffle-broadcast; the
// accumulator lives in registers, so d_out is written exactly once with
// normalization and bias fused in. No atomics, no zero pass, no finalize.
// ---------------------------------------------------------------------------
__global__ void __launch_bounds__(256) gather_kernel(
    const float4* __restrict__ x4,
    const float4* __restrict__ bias4,
    float4*       __restrict__ out4)
{
    const int warp = (blockIdx.x * blockDim.x + threadIdx.x) >> 5;
    const int lane = threadIdx.x & 31;
    if (warp >= N_NODES) return;

    const int start = g_offsets[warp];
    const int end   = g_offsets[warp + 1];

    float4 acc = make_float4(0.f, 0.f, 0.f, 0.f);
    float  deg = 0.f;

    for (int base = start; base < end; base += 32) {
        const int e = base + lane;
        int   c = 0;
        float v = 0.f;
        if (e < end) { c = g_scol[e]; v = g_sval[e]; }
        const int cnt = min(32, end - base);

        #pragma unroll 4
        for (int j = 0; j < cnt; j++) {
            const int   cc = __shfl_sync(0xffffffffu, c, j);
            const float vv = __shfl_sync(0xffffffffu, v, j);
            const float4 xv = x4[(size_t)cc * (D_FEAT / 4) + lane];
            acc.x += vv * xv.x;
            acc.y += vv * xv.y;
            acc.z += vv * xv.z;
            acc.w += vv * xv.w;
            deg   += vv;
        }
    }

    const float inv = (deg == 0.f) ? 0.f : 1.f / deg;
    const float4 b  = bias4[lane];
    float4 o;
    o.x = acc.x * inv + b.x;
    o.y = acc.y * inv + b.y;
    o.z = acc.z * inv + b.z;
    o.w = acc.w * inv + b.w;
    out4[(size_t)warp * (D_FEAT / 4) + lane] = o;
}

// ---------------------------------------------------------------------------
extern "C" void kernel_launch(void* const* d_in, const int* in_sizes, int n_in,
                              void* d_out, int out_size)
{
    const float* x         = (const float*)d_in[0];
    const int*   edge_rows = (const int*)  d_in[1];
    const int*   edge_cols = (const int*)  d_in[2];
    const float* adj_vals  = (const float*)d_in[3];
    const float* bias      = (const float*)d_in[4];
    float*       out       = (float*)d_out;

    (void)in_sizes; (void)n_in; (void)out_size;

    // 1. zero histogram counters
    zero_counts_kernel<<<(N_NODES + 255) / 256, 256>>>();

    // 2. histogram of destination rows
    hist_kernel<<<(N_EDGES + 255) / 256, 256>>>(edge_rows);

    // 3. exclusive scan -> CSR offsets (+ cursor copy)
    scan_kernel<<<1, 1024>>>();

    // 4. counting-sort permute of (col, val)
    permute_kernel<<<(N_EDGES + 255) / 256, 256>>>(edge_rows, edge_cols, adj_vals);

    // 5. warp-per-node gather with fused normalize + bias
    gather_kernel<<<(N_NODES * 32 + 255) / 256, 256>>>(
        (const float4*)x, (const float4*)bias, (float4*)out);
}

// round 9
// speedup vs baseline: 2.1423x; 2.1423x over previous
#include <cuda_runtime.h>
#include <cstdint>

#define N_NODES 40000
#define N_EDGES 640000
#define D_FEAT  128
#define NB_SCAN 157          // ceil(N_NODES / 256)

// ---------------------------------------------------------------------------
// Static scratch (no cudaMalloc allowed).
// ---------------------------------------------------------------------------
__device__ int  g_count  [N_NODES];
__device__ int  g_partial[NB_SCAN];
__device__ int  g_offsets[N_NODES + 1];
__device__ int  g_cursor [N_NODES];
__device__ int2 g_edge   [N_EDGES];      // {col, float-bits of val}

// ---------------------------------------------------------------------------
// Block-wide inclusive scan (256 threads). smem must hold >= 32 ints.
// ---------------------------------------------------------------------------
__device__ __forceinline__ int block_incl_scan(int v, int* smem)
{
    const int lane = threadIdx.x & 31;
    const int wid  = threadIdx.x >> 5;
    #pragma unroll
    for (int o = 1; o < 32; o <<= 1) {
        int n = __shfl_up_sync(0xffffffffu, v, o);
        if (lane >= o) v += n;
    }
    if (lane == 31) smem[wid] = v;
    __syncthreads();
    if (wid == 0) {
        int w = (lane < 8) ? smem[lane] : 0;
        #pragma unroll
        for (int o = 1; o < 8; o <<= 1) {
            int n = __shfl_up_sync(0xffffffffu, w, o);
            if (lane >= o) w += n;
        }
        if (lane < 8) smem[lane] = w;
    }
    __syncthreads();
    if (wid > 0) v += smem[wid - 1];
    return v;
}

// ---------------------------------------------------------------------------
// K1: zero histogram counters.
// ---------------------------------------------------------------------------
__global__ void zero_counts_kernel()
{
    int i = blockIdx.x * blockDim.x + threadIdx.x;
    if (i < N_NODES) g_count[i] = 0;
}

// ---------------------------------------------------------------------------
// K2: histogram of destination rows.
// ---------------------------------------------------------------------------
__global__ void __launch_bounds__(256) hist_kernel(const int* __restrict__ edge_rows)
{
    int i = blockIdx.x * blockDim.x + threadIdx.x;
    if (i < N_EDGES) atomicAdd(&g_count[edge_rows[i]], 1);
}

// ---------------------------------------------------------------------------
// K3a: per-block (256-element) sums of counts -> g_partial.
// ---------------------------------------------------------------------------
__global__ void __launch_bounds__(256) scan_a_kernel()
{
    __shared__ int smem[32];
    const int i    = blockIdx.x * 256 + threadIdx.x;
    const int lane = threadIdx.x & 31;
    const int wid  = threadIdx.x >> 5;

    int v = (i < N_NODES) ? g_count[i] : 0;
    #pragma unroll
    for (int o = 16; o > 0; o >>= 1)
        v += __shfl_down_sync(0xffffffffu, v, o);
    if (lane == 0) smem[wid] = v;
    __syncthreads();
    if (threadIdx.x == 0) {
        int s = 0;
        #pragma unroll
        for (int w = 0; w < 8; w++) s += smem[w];
        g_partial[blockIdx.x] = s;
    }
}

// ---------------------------------------------------------------------------
// K3b: exclusive scan of the 157 block partials (one block).
// ---------------------------------------------------------------------------
__global__ void __launch_bounds__(256) scan_b_kernel()
{
    __shared__ int smem[32];
    const int t = threadIdx.x;
    int p = (t < NB_SCAN) ? g_partial[t] : 0;
    int incl = block_incl_scan(p, smem);
    if (t < NB_SCAN) g_partial[t] = incl - p;   // exclusive
    if (t == 0) g_offsets[N_NODES] = N_EDGES;
}

// ---------------------------------------------------------------------------
// K3c: per-block exclusive scan + block prefix -> offsets & cursor.
// ---------------------------------------------------------------------------
__global__ void __launch_bounds__(256) scan_c_kernel()
{
    __shared__ int smem[32];
    const int i = blockIdx.x * 256 + threadIdx.x;
    int c = (i < N_NODES) ? g_count[i] : 0;
    int incl = block_incl_scan(c, smem);
    int off  = g_partial[blockIdx.x] + incl - c;
    if (i < N_NODES) {
        g_offsets[i] = off;
        g_cursor[i]  = off;
    }
}

// ---------------------------------------------------------------------------
// K4: counting-sort permute; single STG.64 of packed (col, val).
// ---------------------------------------------------------------------------
__global__ void __launch_bounds__(256) permute_kernel(
    const int*   __restrict__ edge_rows,
    const int*   __restrict__ edge_cols,
    const float* __restrict__ adj_vals)
{
    int i = blockIdx.x * blockDim.x + threadIdx.x;
    if (i >= N_EDGES) return;
    const int   r = edge_rows[i];
    const int   c = edge_cols[i];
    const float v = adj_vals[i];
    const int pos = atomicAdd(&g_cursor[r], 1);
    g_edge[pos] = make_int2(c, __float_as_int(v));
}

// ---------------------------------------------------------------------------
// K5: warp-per-node gather, fixed-trip inner loop for batched loads.
// Each lane owns one float4 of the 128-feature row. Edge (col,val) pairs are
// loaded one-per-lane; invalid lanes carry val=0 so the inner loop can run a
// fixed multiple-of-8 trip count (dummy iterations read the hot row-0 line in
// L1 and contribute exactly 0). Normalize + bias fused; out written once.
// ---------------------------------------------------------------------------
__global__ void __launch_bounds__(256) gather_kernel(
    const float4* __restrict__ x4,
    const float4* __restrict__ bias4,
    float4*       __restrict__ out4)
{
    const int warp = (blockIdx.x * blockDim.x + threadIdx.x) >> 5;
    const int lane = threadIdx.x & 31;
    if (warp >= N_NODES) return;

    const int start = g_offsets[warp];
    const int end   = g_offsets[warp + 1];

    float4 acc = make_float4(0.f, 0.f, 0.f, 0.f);
    float  deg = 0.f;

    for (int base = start; base < end; base += 32) {
        const int e = base + lane;
        int2 ev = make_int2(0, 0);            // col=0, val=0.0f for invalid lanes
        if (e < end) ev = g_edge[e];

        const int cnt  = min(32, end - base);
        const int trip = (cnt + 7) & ~7;      // round up to multiple of 8

        #pragma unroll 8
        for (int j = 0; j < trip; j++) {
            const int   cc = __shfl_sync(0xffffffffu, ev.x, j);
            const float vv = __int_as_float(__shfl_sync(0xffffffffu, ev.y, j));
            const float4 xv = x4[(size_t)cc * (D_FEAT / 4) + lane];
            acc.x += vv * xv.x;
            acc.y += vv * xv.y;
            acc.z += vv * xv.z;
            acc.w += vv * xv.w;
            deg   += vv;
        }
    }

    const float inv = (deg == 0.f) ? 0.f : 1.f / deg;
    const float4 b  = bias4[lane];
    float4 o;
    o.x = acc.x * inv + b.x;
    o.y = acc.y * inv + b.y;
    o.z = acc.z * inv + b.z;
    o.w = acc.w * inv + b.w;
    out4[(size_t)warp * (D_FEAT / 4) + lane] = o;
}

// ---------------------------------------------------------------------------
extern "C" void kernel_launch(void* const* d_in, const int* in_sizes, int n_in,
                              void* d_out, int out_size)
{
    const float* x         = (const float*)d_in[0];
    const int*   edge_rows = (const int*)  d_in[1];
    const int*   edge_cols = (const int*)  d_in[2];
    const float* adj_vals  = (const float*)d_in[3];
    const float* bias      = (const float*)d_in[4];
    float*       out       = (float*)d_out;

    (void)in_sizes; (void)n_in; (void)out_size;

    zero_counts_kernel<<<NB_SCAN, 256>>>();
    hist_kernel<<<(N_EDGES + 255) / 256, 256>>>(edge_rows);
    scan_a_kernel<<<NB_SCAN, 256>>>();
    scan_b_kernel<<<1, 256>>>();
    scan_c_kernel<<<NB_SCAN, 256>>>();
    permute_kernel<<<(N_EDGES + 255) / 256, 256>>>(edge_rows, edge_cols, adj_vals);
    gather_kernel<<<(N_NODES * 32 + 255) / 256, 256>>>(
        (const float4*)x, (const float4*)bias, (float4*)out);
}